// round 10
// baseline (speedup 1.0000x reference)
#include <cuda_runtime.h>
#include <cuda_bf16.h>
#include <math.h>

// Problem constants: B=2, L=128, H=768, C=6, nhops=2
#define NC  6
#define LL  128
#define KP  1600     // padded K (1554 -> 1600)
#define MP  640      // padded M (513 -> 640)
#define NF  1536

typedef unsigned int u32;
typedef unsigned short u16;

// Scratch (allocation-free: __device__ globals)
__device__ __align__(16) __nv_bfloat16 g_A[2][2][MP * KP];   // [set][hi/lo], row-major [MP][KP]
__device__ __align__(16) __nv_bfloat16 g_Wt[2][NF * KP];     // [hi/lo], W^T: row n, col k
__device__ __align__(16) float g_clsT[NC * 1536];
__device__ float g_pqr2[2][513 * NC];
__device__ __align__(16) float g_pp[513 * NC * 96];          // probs partials [row*NC+c][slab]

__device__ __forceinline__ void bsplit(float v, u16& h, u16& l) {
    __nv_bfloat16 hb = __float2bfloat16(v);
    __nv_bfloat16 lb = __float2bfloat16(v - __bfloat162float(hb));
    h = *(u16*)&hb; l = *(u16*)&lb;
}
__device__ __forceinline__ u32 smem_u32(const void* p) {
    u32 a;
    asm("{ .reg .u64 t; cvta.to.shared.u64 t, %1; cvt.u32.u64 %0, t; }" : "=r"(a) : "l"(p));
    return a;
}
__device__ __forceinline__ void cpa16(u32 s, const void* g) {
    asm volatile("cp.async.cg.shared.global [%0], [%1], 16;" :: "r"(s), "l"(g));
}
__device__ __forceinline__ void ldsm4(u32* r, u32 addr) {
    asm volatile("ldmatrix.sync.aligned.m8n8.x4.shared.b16 {%0,%1,%2,%3}, [%4];"
        : "=r"(r[0]), "=r"(r[1]), "=r"(r[2]), "=r"(r[3]) : "r"(addr));
}
__device__ __forceinline__ void mma16816(float* c, const u32* a, u32 b0, u32 b1) {
    asm volatile("mma.sync.aligned.m16n8k16.row.col.f32.bf16.bf16.f32 "
        "{%0,%1,%2,%3},{%4,%5,%6,%7},{%8,%9},{%0,%1,%2,%3};"
        : "+f"(c[0]), "+f"(c[1]), "+f"(c[2]), "+f"(c[3])
        : "r"(a[0]), "r"(a[1]), "r"(a[2]), "r"(a[3]), "r"(b0), "r"(b1));
}

// ================= (1) transpose+split feat_w -> g_Wt; clsT piggyback =================
__global__ void k_convW(const float* __restrict__ feat_w, const float* __restrict__ cls_w) {
    __shared__ float ts[32][33];
    int blk = blockIdx.x;                            // 0..2399
    int bk = blk % 50, bn = blk / 50;
    int tx = threadIdx.x & 31, ty = threadIdx.x >> 5;
    #pragma unroll
    for (int i = 0; i < 32; i += 8) {
        int k = bk * 32 + ty + i;
        ts[ty + i][tx] = (k < 1554) ? feat_w[(size_t)k * 1536 + bn * 32 + tx] : 0.f;
    }
    __syncthreads();
    #pragma unroll
    for (int i = 0; i < 32; i += 8) {
        int n = bn * 32 + ty + i;
        int k = bk * 32 + tx;
        u16 h, l; bsplit(ts[tx][ty + i], h, l);
        *(u16*)&g_Wt[0][(size_t)n * KP + k] = h;
        *(u16*)&g_Wt[1][(size_t)n * KP + k] = l;
    }
    if (blk < 36) {
        int t = blk * 256 + threadIdx.x;
        if (t < NC * 1536) {
            int c = t / 1536, k = t % 1536;
            g_clsT[t] = cls_w[k * NC + c];
        }
    }
}

// ================= (2) init: A set0 bf16 hi/lo; zero pads + set1 ext tail =================
__global__ void k_init(const float* __restrict__ hidden) {
    int row = blockIdx.x;                            // 0..639
    for (int c = threadIdx.x; c < KP; c += 256) {
        float v = 0.f;
        if (row < 256)      { if (c < 768) v = hidden[row * 768 + c]; }
        else if (row < 512) { if (c >= 768 && c < 1536) v = hidden[(row - 256) * 768 + c - 768]; }
        u16 h, l; bsplit(v, h, l);
        *(u16*)&g_A[0][0][(size_t)row * KP + c] = h;
        *(u16*)&g_A[0][1][(size_t)row * KP + c] = l;
        if (row >= 513 || c >= 1536) {
            *(u16*)&g_A[1][0][(size_t)row * KP + c] = 0;
            *(u16*)&g_A[1][1][(size_t)row * KP + c] = 0;
        }
    }
}

// ================= (3) hop0: probs + pool + ext, 12 blocks x 256 =================
__global__ void k_pp0(const float* __restrict__ hidden, const float* __restrict__ cls_w,
                      const float* __restrict__ cls_b, const float* __restrict__ am) {
    int b = blockIdx.x / NC, c = blockIdx.x % NC;
    __shared__ float sw[1536];
    __shared__ float sp[LL], sq[LL], sm[LL], sm1[LL], sm2[LL];
    int tid = threadIdx.x;
    for (int e = tid; e < 1536; e += 256) sw[e] = cls_w[e * NC + c];
    __syncthreads();
    int k = tid & 127, isq = tid >> 7;
    {
        const float4* hr = (const float4*)(hidden + (size_t)(b * LL + k) * 768);
        const float4* w  = (const float4*)(sw + isq * 768);
        float s = 0.f;
        #pragma unroll 4
        for (int it = 0; it < 192; it++) {
            float4 a = hr[it], x = w[it];
            s += a.x * x.x + a.y * x.y + a.z * x.z + a.w * x.w;
        }
        if (isq) sq[k] = s; else { sp[k] = s; sm[k] = am[b * LL + k]; }
    }
    __syncthreads();
    float r  = cls_b[c];
    float mk = sm[k], pk = sp[k], qk = sq[k];
    float mx = -INFINITY;
    if (isq == 0) {
        #pragma unroll 4
        for (int i = 0; i < LL; i++) {
            float mv = (i <= k) ? sm[i] * mk : 0.f;
            mx = fmaxf(mx, (sp[i] + qk + r) * mv);
        }
        sm1[k] = mx;
    } else {
        #pragma unroll 4
        for (int i = 0; i < LL; i++) {
            float mv = (i >= k) ? mk * sm[i] : 0.f;
            mx = fmaxf(mx, (pk + sq[i] + r) * mv);
        }
        sm2[k] = mx;
    }
    __syncthreads();
    if (isq) return;
    mx = fmaxf(sm1[k], sm2[k]);
    __nv_bfloat16* Ah = g_A[0][0];
    __nv_bfloat16* Al = g_A[0][1];
    int rowP = b * LL + k, rowQ = 256 + b * LL + k;
    u16 h, l;
    bsplit(mx, h, l);
    *(u16*)&Ah[(size_t)rowP * KP + 1536 + c] = h; *(u16*)&Al[(size_t)rowP * KP + 1536 + c] = l;
    *(u16*)&Ah[(size_t)rowQ * KP + 1542 + c] = h; *(u16*)&Al[(size_t)rowQ * KP + 1542 + c] = l;
    bsplit(pk, h, l);
    *(u16*)&Ah[(size_t)rowP * KP + 1548 + c] = h; *(u16*)&Al[(size_t)rowP * KP + 1548 + c] = l;
    bsplit(qk, h, l);
    *(u16*)&Ah[(size_t)rowQ * KP + 1548 + c] = h; *(u16*)&Al[(size_t)rowQ * KP + 1548 + c] = l;
    if (b == 0 && k == 0) {
        bsplit(r, h, l);
        *(u16*)&Ah[(size_t)512 * KP + 1548 + c] = h; *(u16*)&Al[(size_t)512 * KP + 1548 + c] = l;
    }
}

// ================= hop1 pool+ext from pqr2[src] =================
__global__ void k_poolext(const float* __restrict__ am, int src, int set) {
    int b = blockIdx.x / NC, c = blockIdx.x % NC;
    __shared__ float sp[LL], sq[LL], sm[LL];
    const float* pqr = g_pqr2[src];
    __nv_bfloat16* Ah = g_A[set][0];
    __nv_bfloat16* Al = g_A[set][1];
    int k = threadIdx.x;
    sp[k] = pqr[(b * LL + k) * NC + c];
    sq[k] = pqr[(256 + b * LL + k) * NC + c];
    sm[k] = am[b * LL + k];
    __syncthreads();
    float r  = pqr[512 * NC + c];
    float mk = sm[k], pk = sp[k], qk = sq[k];
    float mx = -INFINITY;
    #pragma unroll 4
    for (int i = 0; i < LL; i++) {
        float mi  = sm[i];
        float mv1 = (i <= k) ? mi * mk : 0.f;
        mx = fmaxf(mx, (sp[i] + qk + r) * mv1);
        float mv2 = (i >= k) ? mk * mi : 0.f;
        mx = fmaxf(mx, (pk + sq[i] + r) * mv2);
    }
    int rowP = b * LL + k, rowQ = 256 + b * LL + k;
    u16 h, l;
    bsplit(mx, h, l);
    *(u16*)&Ah[(size_t)rowP * KP + 1536 + c] = h; *(u16*)&Al[(size_t)rowP * KP + 1536 + c] = l;
    *(u16*)&Ah[(size_t)rowQ * KP + 1542 + c] = h; *(u16*)&Al[(size_t)rowQ * KP + 1542 + c] = l;
    bsplit(pk, h, l);
    *(u16*)&Ah[(size_t)rowP * KP + 1548 + c] = h; *(u16*)&Al[(size_t)rowP * KP + 1548 + c] = l;
    bsplit(qk, h, l);
    *(u16*)&Ah[(size_t)rowQ * KP + 1548 + c] = h; *(u16*)&Al[(size_t)rowQ * KP + 1548 + c] = l;
    if (b == 0 && k == 0) {
        bsplit(r, h, l);
        *(u16*)&Ah[(size_t)512 * KP + 1548 + c] = h; *(u16*)&Al[(size_t)512 * KP + 1548 + c] = l;
    }
}

// ================= HMMA split-bf16 GEMM: 512 threads, 16 warps =================
// CTA 128x64, warp grid 4m x 4n (warp tile 32x16), 3-stage cp.async k64 pipeline.
// Stage layout (pitch 144B): Ah[128r]@0 | Al@18432 | Bh[64r]@36864 | Bl@46080
#define STG2 55296
__global__ void __launch_bounds__(512, 1) k_gemm(int set, const float* __restrict__ bias) {
    extern __shared__ __align__(16) char smem[];
    const __nv_bfloat16* Ah = g_A[set][0];
    const __nv_bfloat16* Al = g_A[set][1];
    __nv_bfloat16* Aoh = g_A[set ^ 1][0];
    __nv_bfloat16* Aol = g_A[set ^ 1][1];

    const int tid = threadIdx.x;
    const int m0 = blockIdx.y * 128, n0 = blockIdx.x * 64;
    const u32 sb = smem_u32(smem);

    const int rt = tid >> 3, ct = (tid & 7) * 16;    // copy: 64 rows x 8 16B-chunks
    const char* gAh = (const char*)Ah + (size_t)(m0 + rt) * (KP * 2) + ct;
    const char* gAl = (const char*)Al + (size_t)(m0 + rt) * (KP * 2) + ct;
    const char* gBh = (const char*)g_Wt[0] + (size_t)(n0 + rt) * (KP * 2) + ct;
    const char* gBl = (const char*)g_Wt[1] + (size_t)(n0 + rt) * (KP * 2) + ct;

    #define COPY_STAGE(s, kt) do {                                               \
        u32 d = sb + (s) * STG2;                                                 \
        int kb = (kt) * 128;                                                     \
        _Pragma("unroll")                                                        \
        for (int i = 0; i < 2; i++) {                                            \
            cpa16(d +         (rt + 64*i) * 144 + ct, gAh + kb + (size_t)i * 64 * (KP*2)); \
            cpa16(d + 18432 + (rt + 64*i) * 144 + ct, gAl + kb + (size_t)i * 64 * (KP*2)); \
        }                                                                        \
        cpa16(d + 36864 + rt * 144 + ct, gBh + kb);                              \
        cpa16(d + 46080 + rt * 144 + ct, gBl + kb);                              \
        asm volatile("cp.async.commit_group;" ::: "memory");                     \
    } while (0)

    COPY_STAGE(0, 0);
    COPY_STAGE(1, 1);

    const int wid = tid >> 5, lane = tid & 31;
    const int wm = wid & 3, wn = wid >> 2;           // warp grid 4(m) x 4(n)
    const int g = lane >> 2, t = lane & 3;
    const u32 arow = (u32)((wm * 32 + (lane & 15)) * 144 + ((lane >> 4) << 4));
    const u32 brow = (u32)(36864 + (wn * 16 + (lane & 15)) * 144 + ((lane >> 4) << 4));

    float acc[2][2][4];
    #pragma unroll
    for (int mt = 0; mt < 2; mt++)
        #pragma unroll
        for (int nt = 0; nt < 2; nt++)
            #pragma unroll
            for (int i = 0; i < 4; i++) acc[mt][nt][i] = 0.f;

    for (int kt = 0; kt < 25; kt++) {
        if (kt < 24) asm volatile("cp.async.wait_group 1;" ::: "memory");
        else         asm volatile("cp.async.wait_group 0;" ::: "memory");
        __syncthreads();
        u32 st = sb + (kt % 3) * STG2;
        u32 aH = st + arow;
        u32 bH = st + brow;
        #pragma unroll
        for (int kk = 0; kk < 4; kk++) {             // four k16 steps (k64 per stage)
            u32 ah[2][4], al[2][4], bh[4], bl[4];
            ldsm4(ah[0], aH + kk * 32);
            ldsm4(ah[1], aH + 2304 + kk * 32);       // mt=1: +16 rows * 144
            ldsm4(al[0], aH + 18432 + kk * 32);
            ldsm4(al[1], aH + 18432 + 2304 + kk * 32);
            ldsm4(bh, bH + kk * 32);                 // r0,r1 = n0-7,n8-15 kh0; r2,r3 = kh1
            ldsm4(bl, bH + 9216 + kk * 32);
            #pragma unroll
            for (int mt = 0; mt < 2; mt++) {
                mma16816(acc[mt][0], ah[mt], bh[0], bh[2]);
                mma16816(acc[mt][0], ah[mt], bl[0], bl[2]);
                mma16816(acc[mt][0], al[mt], bh[0], bh[2]);
                mma16816(acc[mt][1], ah[mt], bh[1], bh[3]);
                mma16816(acc[mt][1], ah[mt], bl[1], bl[3]);
                mma16816(acc[mt][1], al[mt], bh[1], bh[3]);
            }
        }
        if (kt + 2 < 25) COPY_STAGE((kt + 2) % 3, kt + 2);
    }

    // ---- epilogue ----
    #pragma unroll
    for (int mt = 0; mt < 2; mt++)
        #pragma unroll
        for (int half = 0; half < 2; half++) {
            int r = m0 + wm * 32 + mt * 16 + g + half * 8;
            if (r == 512) {
                #pragma unroll
                for (int nt = 0; nt < 2; nt++) {
                    int col = n0 + wn * 16 + nt * 8 + t * 2;
                    acc[mt][nt][half * 2]     += bias[col];
                    acc[mt][nt][half * 2 + 1] += bias[col + 1];
                }
            }
        }

    // next-hop bf16 hi/lo A
    #pragma unroll
    for (int mt = 0; mt < 2; mt++)
        #pragma unroll
        for (int nt = 0; nt < 2; nt++) {
            int col = n0 + wn * 16 + nt * 8 + t * 2;
            #pragma unroll
            for (int half = 0; half < 2; half++) {
                int r = m0 + wm * 32 + mt * 16 + g + half * 8;
                if (r < 513) {
                    u16 h0, l0, h1, l1;
                    bsplit(acc[mt][nt][half * 2], h0, l0);
                    bsplit(acc[mt][nt][half * 2 + 1], h1, l1);
                    *(u32*)(Aoh + (size_t)r * KP + col) = (u32)h0 | ((u32)h1 << 16);
                    *(u32*)(Aol + (size_t)r * KP + col) = (u32)l0 | ((u32)l1 << 16);
                }
            }
        }

    // probs partials, transposed layout: g_pp[(r*NC+c)*96 + slab]
    int slab = blockIdx.x * 4 + wn;                  // 0..95
    #pragma unroll
    for (int c = 0; c < NC; c++) {
        float cv[2][2];
        #pragma unroll
        for (int nt = 0; nt < 2; nt++) {
            int col = n0 + wn * 16 + nt * 8 + t * 2;
            cv[nt][0] = g_clsT[c * 1536 + col];
            cv[nt][1] = g_clsT[c * 1536 + col + 1];
        }
        #pragma unroll
        for (int mt = 0; mt < 2; mt++)
            #pragma unroll
            for (int half = 0; half < 2; half++) {
                float s = 0.f;
                #pragma unroll
                for (int nt = 0; nt < 2; nt++)
                    s += acc[mt][nt][half * 2] * cv[nt][0]
                       + acc[mt][nt][half * 2 + 1] * cv[nt][1];
                s += __shfl_xor_sync(0xffffffffu, s, 1);
                s += __shfl_xor_sync(0xffffffffu, s, 2);
                if (t == 0) {
                    int r = m0 + wm * 32 + mt * 16 + g + half * 8;
                    if (r < 513) g_pp[(size_t)(r * NC + c) * 96 + slab] = s;
                }
            }
    }
    #undef COPY_STAGE
}

// ================= reduce probs partials (coalesced) =================
__global__ void k_red(int dst, const float* __restrict__ cls_b) {
    int idx = blockIdx.x * 256 + threadIdx.x;
    if (idx >= 513 * NC) return;
    const float4* pp = (const float4*)(g_pp + (size_t)idx * 96);
    float s = 0.f;
    #pragma unroll
    for (int i = 0; i < 24; i++) {
        float4 v = pp[i];
        s += v.x + v.y + v.z + v.w;
    }
    if (idx >= 512 * NC) s += cls_b[idx - 512 * NC];
    g_pqr2[dst][idx] = s;
}

// ================= final: logits[b,i,j,c] = p + q + r =================
__global__ void k_out(float* __restrict__ out) {
    int idx = blockIdx.x * 256 + threadIdx.x;        // 0..196607 exact
    int c = idx % NC;
    int j = (idx / NC) % LL;
    int t = idx / (NC * LL);
    int i = t % LL;
    int b = t / LL;
    const float* pqr = g_pqr2[0];
    out[idx] = pqr[(b * LL + i) * NC + c]
             + pqr[(256 + b * LL + j) * NC + c]
             + pqr[512 * NC + c];
}

extern "C" void kernel_launch(void* const* d_in, const int* in_sizes, int n_in,
                              void* d_out, int out_size) {
    const float* hidden = (const float*)d_in[0];
    const float* am     = (const float*)d_in[1];
    const float* cls_w  = (const float*)d_in[2];
    const float* cls_b  = (const float*)d_in[3];
    const float* feat_w = (const float*)d_in[4];
    const float* feat_b = (const float*)d_in[5];

    cudaFuncSetAttribute(k_gemm, cudaFuncAttributeMaxDynamicSharedMemorySize, 3 * STG2);

    k_convW<<<2400, 256>>>(feat_w, cls_w);           // (1)
    k_init<<<MP, 256>>>(hidden);                     // (2)
    k_pp0<<<12, 256>>>(hidden, cls_w, cls_b, am);    // (3)
    k_gemm<<<dim3(24, 5), 512, 3 * STG2>>>(0, feat_b); // (4) <- profiled
    k_red<<<13, 256>>>(1, cls_b);                    // (5)
    k_poolext<<<12, 128>>>(am, 1, 1);                // (6)
    k_gemm<<<dim3(24, 5), 512, 3 * STG2>>>(1, feat_b); // (7)
    k_red<<<13, 256>>>(0, cls_b);                    // (8)
    k_out<<<768, 256>>>((float*)d_out);              // (9)
}

// round 11
// speedup vs baseline: 1.7654x; 1.7654x over previous
#include <cuda_runtime.h>
#include <cuda_bf16.h>
#include <math.h>

// Problem constants: B=2, L=128, H=768, C=6, nhops=2
#define NC  6
#define LL  128
#define KP  1600     // padded K (1554 -> 1600)
#define MP  640      // padded M (513 -> 640)
#define NF  1536

typedef unsigned int u32;
typedef unsigned short u16;

// Scratch (allocation-free: __device__ globals)
__device__ __align__(16) __nv_bfloat16 g_Ah[MP * KP];        // hop0 A hi, row-major [MP][KP]
__device__ __align__(16) __nv_bfloat16 g_Al[MP * KP];        // hop0 A lo
__device__ __align__(16) __nv_bfloat16 g_Wt[2][NF * KP];     // [hi/lo], W^T: row n, col k
__device__ __align__(16) float g_clsT[NC * 1536];
__device__ __align__(16) float g_WcT[NC * KP];               // (feat_w@cls_w)^T: [c][k], k<1554
__device__ __align__(16) float g_X[513 * 1536];              // fp32 features1
__device__ float g_pqr2[2][513 * NC];
__device__ __align__(16) float g_pp[513 * NC * 48];          // probs1 partials [row*NC+c][slab]
__device__ float g_pooled[2 * LL * NC];                      // hop1 pooled

__device__ __forceinline__ void bsplit(float v, u16& h, u16& l) {
    __nv_bfloat16 hb = __float2bfloat16(v);
    __nv_bfloat16 lb = __float2bfloat16(v - __bfloat162float(hb));
    h = *(u16*)&hb; l = *(u16*)&lb;
}
__device__ __forceinline__ u32 smem_u32(const void* p) {
    u32 a;
    asm("{ .reg .u64 t; cvta.to.shared.u64 t, %1; cvt.u32.u64 %0, t; }" : "=r"(a) : "l"(p));
    return a;
}
__device__ __forceinline__ void cpa16(u32 s, const void* g) {
    asm volatile("cp.async.cg.shared.global [%0], [%1], 16;" :: "r"(s), "l"(g));
}
__device__ __forceinline__ void ldsm4(u32* r, u32 addr) {
    asm volatile("ldmatrix.sync.aligned.m8n8.x4.shared.b16 {%0,%1,%2,%3}, [%4];"
        : "=r"(r[0]), "=r"(r[1]), "=r"(r[2]), "=r"(r[3]) : "r"(addr));
}
__device__ __forceinline__ void mma16816(float* c, const u32* a, u32 b0, u32 b1) {
    asm volatile("mma.sync.aligned.m16n8k16.row.col.f32.bf16.bf16.f32 "
        "{%0,%1,%2,%3},{%4,%5,%6,%7},{%8,%9},{%0,%1,%2,%3};"
        : "+f"(c[0]), "+f"(c[1]), "+f"(c[2]), "+f"(c[3])
        : "r"(a[0]), "r"(a[1]), "r"(a[2]), "r"(a[3]), "r"(b0), "r"(b1));
}

// ================= (1) transpose+split feat_w -> g_Wt; clsT piggyback =================
__global__ void k_convW(const float* __restrict__ feat_w, const float* __restrict__ cls_w) {
    __shared__ float ts[32][33];
    int blk = blockIdx.x;                            // 0..2399
    int bk = blk % 50, bn = blk / 50;
    int tx = threadIdx.x & 31, ty = threadIdx.x >> 5;
    #pragma unroll
    for (int i = 0; i < 32; i += 8) {
        int k = bk * 32 + ty + i;
        ts[ty + i][tx] = (k < 1554) ? feat_w[(size_t)k * 1536 + bn * 32 + tx] : 0.f;
    }
    __syncthreads();
    #pragma unroll
    for (int i = 0; i < 32; i += 8) {
        int n = bn * 32 + ty + i;
        int k = bk * 32 + tx;
        u16 h, l; bsplit(ts[tx][ty + i], h, l);
        *(u16*)&g_Wt[0][(size_t)n * KP + k] = h;
        *(u16*)&g_Wt[1][(size_t)n * KP + k] = l;
    }
    if (blk < 36) {
        int t = blk * 256 + threadIdx.x;
        if (t < NC * 1536) {
            int c = t / 1536, k = t % 1536;
            g_clsT[t] = cls_w[k * NC + c];
        }
    }
}

// ================= (2) init: A bf16 hi/lo only in the k-regions the GEMM reads =========
__global__ void k_init(const float* __restrict__ hidden) {
    int row = blockIdx.x;                            // 0..639
    int tid = threadIdx.x;
    if (row < 256) {                                 // P rows: k in [0,768)
        for (int c = tid; c < 768; c += 256) {
            u16 h, l; bsplit(hidden[(size_t)row * 768 + c], h, l);
            *(u16*)&g_Ah[(size_t)row * KP + c] = h;
            *(u16*)&g_Al[(size_t)row * KP + c] = l;
        }
    } else if (row < 512) {                          // Q rows: k in [768,1536)
        for (int c = tid; c < 768; c += 256) {
            u16 h, l; bsplit(hidden[(size_t)(row - 256) * 768 + c], h, l);
            *(u16*)&g_Ah[(size_t)row * KP + 768 + c] = h;
            *(u16*)&g_Al[(size_t)row * KP + 768 + c] = l;
        }
    }
    if (tid < 64) {                                  // ext tail [1536,1600) zero for all rows
        *(u16*)&g_Ah[(size_t)row * KP + 1536 + tid] = 0;
        *(u16*)&g_Al[(size_t)row * KP + 1536 + tid] = 0;
    }
}

// ================= (3) hop0: probs + pool + ext, 12 blocks x 256 =================
__global__ void k_pp0(const float* __restrict__ hidden, const float* __restrict__ cls_w,
                      const float* __restrict__ cls_b, const float* __restrict__ am) {
    int b = blockIdx.x / NC, c = blockIdx.x % NC;
    __shared__ float sw[1536];
    __shared__ float sp[LL], sq[LL], sm[LL], sm1[LL], sm2[LL];
    int tid = threadIdx.x;
    for (int e = tid; e < 1536; e += 256) sw[e] = cls_w[e * NC + c];
    __syncthreads();
    int k = tid & 127, isq = tid >> 7;
    {
        const float4* hr = (const float4*)(hidden + (size_t)(b * LL + k) * 768);
        const float4* w  = (const float4*)(sw + isq * 768);
        float s = 0.f;
        #pragma unroll 4
        for (int it = 0; it < 192; it++) {
            float4 a = hr[it], x = w[it];
            s += a.x * x.x + a.y * x.y + a.z * x.z + a.w * x.w;
        }
        if (isq) sq[k] = s; else { sp[k] = s; sm[k] = am[b * LL + k]; }
    }
    __syncthreads();
    float r  = cls_b[c];
    float mk = sm[k], pk = sp[k], qk = sq[k];
    float mx = -INFINITY;
    if (isq == 0) {
        #pragma unroll 4
        for (int i = 0; i < LL; i++) {
            float mv = (i <= k) ? sm[i] * mk : 0.f;
            mx = fmaxf(mx, (sp[i] + qk + r) * mv);
        }
        sm1[k] = mx;
    } else {
        #pragma unroll 4
        for (int i = 0; i < LL; i++) {
            float mv = (i >= k) ? mk * sm[i] : 0.f;
            mx = fmaxf(mx, (pk + sq[i] + r) * mv);
        }
        sm2[k] = mx;
    }
    __syncthreads();
    if (isq) return;
    mx = fmaxf(sm1[k], sm2[k]);
    int rowP = b * LL + k, rowQ = 256 + b * LL + k;
    u16 h, l;
    bsplit(mx, h, l);
    *(u16*)&g_Ah[(size_t)rowP * KP + 1536 + c] = h; *(u16*)&g_Al[(size_t)rowP * KP + 1536 + c] = l;
    *(u16*)&g_Ah[(size_t)rowQ * KP + 1542 + c] = h; *(u16*)&g_Al[(size_t)rowQ * KP + 1542 + c] = l;
    bsplit(pk, h, l);
    *(u16*)&g_Ah[(size_t)rowP * KP + 1548 + c] = h; *(u16*)&g_Al[(size_t)rowP * KP + 1548 + c] = l;
    bsplit(qk, h, l);
    *(u16*)&g_Ah[(size_t)rowQ * KP + 1548 + c] = h; *(u16*)&g_Al[(size_t)rowQ * KP + 1548 + c] = l;
    if (b == 0 && k == 0) {
        bsplit(r, h, l);
        *(u16*)&g_Ah[(size_t)512 * KP + 1548 + c] = h; *(u16*)&g_Al[(size_t)512 * KP + 1548 + c] = l;
    }
}

// ================= (4) hop0 HMMA GEMM with block-sparse k schedule =================
// CTA 128x64, 8 warps (4m x 2n, warp tile 32x32), 3-stage cp.async k64 pipeline.
// mt 0,1 (P rows): k tiles {0..11} + ext; mt 2,3 (Q): {12..23} + ext; mt 4: ext only.
// Epilogue: fp32 features1 -> g_X, probs1 partials -> g_pp.
#define STG2 55296
__global__ void __launch_bounds__(256, 1) k_gemm(const float* __restrict__ bias) {
    extern __shared__ __align__(16) char smem[];
    const int tid = threadIdx.x;
    const int mty = blockIdx.y;
    const int m0 = mty * 128, n0 = blockIdx.x * 64;
    const u32 sb = smem_u32(smem);

    const int cnt   = (mty < 4) ? 13 : 1;
    const int kbase = (mty < 2) ? 0 : 12;

    const int rt = tid >> 3, ct = (tid & 7) * 16;    // copy: 32 rows x 8 16B-chunks
    const char* gAh = (const char*)g_Ah + (size_t)(m0 + rt) * (KP * 2) + ct;
    const char* gAl = (const char*)g_Al + (size_t)(m0 + rt) * (KP * 2) + ct;
    const char* gBh = (const char*)g_Wt[0] + (size_t)(n0 + rt) * (KP * 2) + ct;
    const char* gBl = (const char*)g_Wt[1] + (size_t)(n0 + rt) * (KP * 2) + ct;

    #define COPY_STAGE(s, it) do {                                               \
        u32 d = sb + (s) * STG2;                                                 \
        int ii = ((it) < cnt - 1) ? (it) : cnt - 1;                              \
        int kb = (ii == cnt - 1) ? 3072 : (kbase + ii) * 128;                    \
        _Pragma("unroll")                                                        \
        for (int i = 0; i < 4; i++) {                                            \
            cpa16(d +         (rt + 32*i) * 144 + ct, gAh + kb + (size_t)i * 32 * (KP*2)); \
            cpa16(d + 18432 + (rt + 32*i) * 144 + ct, gAl + kb + (size_t)i * 32 * (KP*2)); \
        }                                                                        \
        _Pragma("unroll")                                                        \
        for (int i = 0; i < 2; i++) {                                            \
            cpa16(d + 36864 + (rt + 32*i) * 144 + ct, gBh + kb + (size_t)i * 32 * (KP*2)); \
            cpa16(d + 46080 + (rt + 32*i) * 144 + ct, gBl + kb + (size_t)i * 32 * (KP*2)); \
        }                                                                        \
        asm volatile("cp.async.commit_group;" ::: "memory");                     \
    } while (0)

    COPY_STAGE(0, 0);
    COPY_STAGE(1, 1);

    const int wid = tid >> 5, lane = tid & 31;
    const int wm = wid & 3, wn = wid >> 2;           // warp grid 4(m) x 2(n)
    const int g = lane >> 2, t = lane & 3;
    const u32 arow = (u32)((wm * 32 + (lane & 15)) * 144 + ((lane >> 4) << 4));
    const u32 brow = (u32)(36864 + (wn * 32 + lane) * 144);

    float acc[2][4][4];
    #pragma unroll
    for (int mt = 0; mt < 2; mt++)
        #pragma unroll
        for (int nt = 0; nt < 4; nt++)
            #pragma unroll
            for (int i = 0; i < 4; i++) acc[mt][nt][i] = 0.f;

    for (int kt = 0; kt < cnt; kt++) {
        if (kt < cnt - 1) asm volatile("cp.async.wait_group 1;" ::: "memory");
        else              asm volatile("cp.async.wait_group 0;" ::: "memory");
        __syncthreads();
        u32 st = sb + (kt % 3) * STG2;
        u32 aH = st + arow;
        u32 bH = st + brow;
        #pragma unroll
        for (int kk = 0; kk < 4; kk++) {             // four k16 steps (k64 per stage)
            u32 ah[2][4], al[2][4], bh0[4], bh1[4], bl0[4], bl1[4];
            ldsm4(ah[0], aH + kk * 32);
            ldsm4(ah[1], aH + 2304 + kk * 32);
            ldsm4(al[0], aH + 18432 + kk * 32);
            ldsm4(al[1], aH + 18432 + 2304 + kk * 32);
            ldsm4(bh0, bH + kk * 32);
            ldsm4(bh1, bH + kk * 32 + 16);
            ldsm4(bl0, bH + 9216 + kk * 32);
            ldsm4(bl1, bH + 9216 + kk * 32 + 16);
            #pragma unroll
            for (int nt = 0; nt < 4; nt++)
                #pragma unroll
                for (int mt = 0; mt < 2; mt++) {
                    mma16816(acc[mt][nt], ah[mt], bh0[nt], bh1[nt]);
                    mma16816(acc[mt][nt], ah[mt], bl0[nt], bl1[nt]);
                    mma16816(acc[mt][nt], al[mt], bh0[nt], bh1[nt]);
                }
        }
        if (kt + 2 < cnt) COPY_STAGE((kt + 2) % 3, kt + 2);
    }

    // ---- epilogue ----
    #pragma unroll
    for (int mt = 0; mt < 2; mt++)
        #pragma unroll
        for (int half = 0; half < 2; half++) {
            int r = m0 + wm * 32 + mt * 16 + g + half * 8;
            if (r == 512) {
                #pragma unroll
                for (int nt = 0; nt < 4; nt++) {
                    int col = n0 + wn * 32 + nt * 8 + t * 2;
                    acc[mt][nt][half * 2]     += bias[col];
                    acc[mt][nt][half * 2 + 1] += bias[col + 1];
                }
            }
        }

    // fp32 features1
    #pragma unroll
    for (int mt = 0; mt < 2; mt++)
        #pragma unroll
        for (int nt = 0; nt < 4; nt++) {
            int col = n0 + wn * 32 + nt * 8 + t * 2;
            #pragma unroll
            for (int half = 0; half < 2; half++) {
                int r = m0 + wm * 32 + mt * 16 + g + half * 8;
                if (r < 513) {
                    float2 o;
                    o.x = acc[mt][nt][half * 2];
                    o.y = acc[mt][nt][half * 2 + 1];
                    *(float2*)(g_X + (size_t)r * 1536 + col) = o;
                }
            }
        }

    // probs1 partials: g_pp[(r*NC+c)*48 + slab]
    int slab = blockIdx.x * 2 + wn;                  // 0..47
    #pragma unroll
    for (int c = 0; c < NC; c++) {
        float cv[4][2];
        #pragma unroll
        for (int nt = 0; nt < 4; nt++) {
            int col = n0 + wn * 32 + nt * 8 + t * 2;
            cv[nt][0] = g_clsT[c * 1536 + col];
            cv[nt][1] = g_clsT[c * 1536 + col + 1];
        }
        #pragma unroll
        for (int mt = 0; mt < 2; mt++)
            #pragma unroll
            for (int half = 0; half < 2; half++) {
                float s = 0.f;
                #pragma unroll
                for (int nt = 0; nt < 4; nt++)
                    s += acc[mt][nt][half * 2] * cv[nt][0]
                       + acc[mt][nt][half * 2 + 1] * cv[nt][1];
                s += __shfl_xor_sync(0xffffffffu, s, 1);
                s += __shfl_xor_sync(0xffffffffu, s, 2);
                if (t == 0) {
                    int r = m0 + wm * 32 + mt * 16 + g + half * 8;
                    if (r < 513) g_pp[(size_t)(r * NC + c) * 48 + slab] = s;
                }
            }
    }
    #undef COPY_STAGE
}

// ================= (5) reduce probs1 partials -> pqr2[1] =================
__global__ void k_red(const float* __restrict__ cls_b) {
    int idx = blockIdx.x * 256 + threadIdx.x;
    if (idx >= 513 * NC) return;
    const float4* pp = (const float4*)(g_pp + (size_t)idx * 48);
    float s = 0.f;
    #pragma unroll
    for (int i = 0; i < 12; i++) {
        float4 v = pp[i];
        s += v.x + v.y + v.z + v.w;
    }
    if (idx >= 512 * NC) s += cls_b[idx - 512 * NC];
    g_pqr2[1][idx] = s;
}

// ================= (6) hop1 pool from pqr2[1] -> g_pooled (fp32) =================
__global__ void k_poolext1(const float* __restrict__ am) {
    int b = blockIdx.x / NC, c = blockIdx.x % NC;
    __shared__ float sp[LL], sq[LL], sm[LL];
    const float* pqr = g_pqr2[1];
    int k = threadIdx.x;
    sp[k] = pqr[(b * LL + k) * NC + c];
    sq[k] = pqr[(256 + b * LL + k) * NC + c];
    sm[k] = am[b * LL + k];
    __syncthreads();
    float r  = pqr[512 * NC + c];
    float mk = sm[k], pk = sp[k], qk = sq[k];
    float mx = -INFINITY;
    #pragma unroll 4
    for (int i = 0; i < LL; i++) {
        float mi  = sm[i];
        float mv1 = (i <= k) ? mi * mk : 0.f;
        mx = fmaxf(mx, (sp[i] + qk + r) * mv1);
        float mv2 = (i >= k) ? mk * mi : 0.f;
        mx = fmaxf(mx, (pk + sq[i] + r) * mv2);
    }
    g_pooled[(b * LL + k) * NC + c] = mx;
}

// ================= (7) Wc = feat_w @ cls_w, stored transposed [c][k] =================
__global__ void k_Wc(const float* __restrict__ feat_w) {
    int k = blockIdx.x;                              // 0..1599
    int c = threadIdx.x >> 5, lane = threadIdx.x & 31;
    float s = 0.f;
    if (k < 1554) {
        const float4* fr = (const float4*)(feat_w + (size_t)k * 1536);
        const float4* wr = (const float4*)(g_clsT + c * 1536);
        #pragma unroll
        for (int it = 0; it < 12; it++) {
            int k4 = it * 32 + lane;
            float4 a = fr[k4], b = wr[k4];
            s += a.x * b.x + a.y * b.y + a.z * b.z + a.w * b.w;
        }
        #pragma unroll
        for (int o = 16; o; o >>= 1) s += __shfl_down_sync(0xffffffffu, s, o);
    }
    if (lane == 0) g_WcT[c * KP + k] = (k < 1554) ? s : 0.f;
}

// ================= (8) probs2 = [features1 | ext1] @ Wc -> pqr2[0] =================
__global__ void k_probs2(const float* __restrict__ cls_b) {
    int row = blockIdx.x;                            // 0..512
    int c = threadIdx.x >> 5, lane = threadIdx.x & 31;
    const float4* xr = (const float4*)(g_X + (size_t)row * 1536);
    const float4* wr = (const float4*)(g_WcT + c * KP);
    float s = 0.f;
    #pragma unroll
    for (int it = 0; it < 12; it++) {
        int k4 = it * 32 + lane;
        float4 a = xr[k4], b = wr[k4];
        s += a.x * b.x + a.y * b.y + a.z * b.z + a.w * b.w;
    }
    #pragma unroll
    for (int o = 16; o; o >>= 1) s += __shfl_down_sync(0xffffffffu, s, o);
    if (lane == 0) {
        const float* wc = g_WcT + c * KP + 1536;
        #pragma unroll
        for (int t = 0; t < 18; t++) {
            float e;
            if (t < 6)       e = (row < 256) ? g_pooled[row * NC + t] : 0.f;
            else if (t < 12) e = (row >= 256 && row < 512) ? g_pooled[(row - 256) * NC + t - 6] : 0.f;
            else             e = g_pqr2[1][row * NC + t - 12];
            s += e * wc[t];
        }
        if (row == 512) s += cls_b[c];
        g_pqr2[0][row * NC + c] = s;
    }
}

// ================= (9) final: logits[b,i,j,c] = p + q + r =================
__global__ void k_out(float* __restrict__ out) {
    int idx = blockIdx.x * 256 + threadIdx.x;        // 0..196607 exact
    int c = idx % NC;
    int j = (idx / NC) % LL;
    int t = idx / (NC * LL);
    int i = t % LL;
    int b = t / LL;
    const float* pqr = g_pqr2[0];
    out[idx] = pqr[(b * LL + i) * NC + c]
             + pqr[(256 + b * LL + j) * NC + c]
             + pqr[512 * NC + c];
}

extern "C" void kernel_launch(void* const* d_in, const int* in_sizes, int n_in,
                              void* d_out, int out_size) {
    const float* hidden = (const float*)d_in[0];
    const float* am     = (const float*)d_in[1];
    const float* cls_w  = (const float*)d_in[2];
    const float* cls_b  = (const float*)d_in[3];
    const float* feat_w = (const float*)d_in[4];
    const float* feat_b = (const float*)d_in[5];

    cudaFuncSetAttribute(k_gemm, cudaFuncAttributeMaxDynamicSharedMemorySize, 3 * STG2);

    k_convW<<<2400, 256>>>(feat_w, cls_w);               // (1)
    k_init<<<MP, 256>>>(hidden);                         // (2)
    k_pp0<<<12, 256>>>(hidden, cls_w, cls_b, am);        // (3)
    k_gemm<<<dim3(24, 5), 256, 3 * STG2>>>(feat_b);      // (4) <- profiled
    k_red<<<13, 256>>>(cls_b);                           // (5) -> pqr2[1]
    k_poolext1<<<12, 128>>>(am);                         // (6)
    k_Wc<<<1600, 192>>>(feat_w);                         // (7)
    k_probs2<<<513, 192>>>(cls_b);                       // (8) -> pqr2[0]
    k_out<<<768, 256>>>((float*)d_out);                  // (9)
}

// round 13
// speedup vs baseline: 2.5144x; 1.4242x over previous
#include <cuda_runtime.h>
#include <math.h>

// Problem constants: B=2, L=128, H=768, C=6, nhops=2
#define NC  6
#define LL  128
#define WS  1600     // WT row stride (1554 padded)

typedef unsigned int u32;

// Scratch (allocation-free: __device__ globals)
__device__ __align__(16) float g_clsT[NC * 1536];    // cls_w^T [c][k]
__device__ __align__(16) float g_WcT[NC * WS];       // (feat_w@cls_w)^T [c][k], k<1554
__device__ __align__(16) float g_W2T[NC * WS];       // (feat_w@Wc1)^T   [c][k], k<1554
__device__ float g_fbc[NC];                          // feat_b @ cls_w
__device__ float g_fbW2[NC];                         // feat_b @ Wc1
__device__ float g_pqr0[513 * NC], g_pool0[256 * NC];
__device__ float g_pqr1[513 * NC], g_pool1[256 * NC];
__device__ float g_pqr2f[513 * NC];

// ================= (1) clsT build =================
__global__ void k_cls(const float* __restrict__ cls_w) {
    int idx = blockIdx.x * 256 + threadIdx.x;        // 0..9215 exact (36 blocks)
    int c = idx / 1536, k = idx % 1536;
    g_clsT[idx] = cls_w[k * NC + c];
}

// ================= (2) hop0: p0/q0 + masked max-pool =================
// 12 blocks (b,c) x 256 threads
__global__ void k_pp0(const float* __restrict__ hidden, const float* __restrict__ cls_w,
                      const float* __restrict__ cls_b, const float* __restrict__ am) {
    int b = blockIdx.x / NC, c = blockIdx.x % NC;
    __shared__ float sw[1536];
    __shared__ float sp[LL], sq[LL], sm[LL], sm1[LL], sm2[LL];
    int tid = threadIdx.x;
    for (int e = tid; e < 1536; e += 256) sw[e] = cls_w[e * NC + c];
    __syncthreads();
    int k = tid & 127, isq = tid >> 7;               // half 0: p-dot, half 1: q-dot
    {
        const float4* hr = (const float4*)(hidden + (size_t)(b * LL + k) * 768);
        const float4* w  = (const float4*)(sw + isq * 768);
        float s = 0.f;
        #pragma unroll 4
        for (int it = 0; it < 192; it++) {
            float4 a = hr[it], x = w[it];
            s += a.x * x.x + a.y * x.y + a.z * x.z + a.w * x.w;
        }
        if (isq) sq[k] = s; else { sp[k] = s; sm[k] = am[b * LL + k]; }
    }
    __syncthreads();
    float r  = cls_b[c];
    float mk = sm[k], pk = sp[k], qk = sq[k];
    float mx = -INFINITY;
    if (isq == 0) {                                  // column k: over i <= k
        #pragma unroll 4
        for (int i = 0; i < LL; i++) {
            float mv = (i <= k) ? sm[i] * mk : 0.f;
            mx = fmaxf(mx, (sp[i] + qk + r) * mv);
        }
        sm1[k] = mx;
    } else {                                         // row k: over j >= k
        #pragma unroll 4
        for (int i = 0; i < LL; i++) {
            float mv = (i >= k) ? mk * sm[i] : 0.f;
            mx = fmaxf(mx, (pk + sq[i] + r) * mv);
        }
        sm2[k] = mx;
    }
    __syncthreads();
    if (isq) return;
    int rw = b * LL + k;
    g_pool0[rw * NC + c] = fmaxf(sm1[k], sm2[k]);
    g_pqr0[rw * NC + c] = pk;
    g_pqr0[(256 + rw) * NC + c] = qk;
    if (b == 0 && k == 0) g_pqr0[512 * NC + c] = r;
}

// ================= (3,4) weight condensation =================
// which=0: Wc = feat_w @ cls_w (in: g_clsT, stride 1536; out: g_WcT, g_fbc)
// which=1: W2 = feat_w @ Wc1   (in: g_WcT, stride WS;   out: g_W2T, g_fbW2)
// 1601 blocks x 192 threads (6 warps = 6 channels); block 1600 does feat_b dot.
__global__ void k_dotW(const float* __restrict__ feat_w, const float* __restrict__ feat_b,
                       int which) {
    int k = blockIdx.x;
    int c = threadIdx.x >> 5, lane = threadIdx.x & 31;
    const float* in  = which ? (g_WcT + (size_t)c * WS) : (g_clsT + (size_t)c * 1536);
    const float4* wr = (const float4*)in;
    if (k < WS) {
        float s = 0.f;
        if (k < 1554) {
            const float4* fr = (const float4*)(feat_w + (size_t)k * 1536);
            #pragma unroll
            for (int it = 0; it < 12; it++) {
                int k4 = it * 32 + lane;
                float4 a = fr[k4], b = wr[k4];
                s += a.x * b.x + a.y * b.y + a.z * b.z + a.w * b.w;
            }
            #pragma unroll
            for (int o = 16; o; o >>= 1) s += __shfl_down_sync(0xffffffffu, s, o);
        }
        if (lane == 0) {
            float v = (k < 1554) ? s : 0.f;
            if (which) g_W2T[c * WS + k] = v; else g_WcT[c * WS + k] = v;
        }
    } else {
        const float4* fr = (const float4*)feat_b;
        float s = 0.f;
        #pragma unroll
        for (int it = 0; it < 12; it++) {
            int k4 = it * 32 + lane;
            float4 a = fr[k4], b = wr[k4];
            s += a.x * b.x + a.y * b.y + a.z * b.z + a.w * b.w;
        }
        #pragma unroll
        for (int o = 16; o; o >>= 1) s += __shfl_down_sync(0xffffffffu, s, o);
        if (lane == 0) {
            if (which) g_fbW2[c] = s; else g_fbc[c] = s;
        }
    }
}

// ================= (5) probs1 = A0ext @ Wc (+ const-row terms) =================
// 513 blocks x 192 threads
__global__ void k_probs1(const float* __restrict__ hidden, const float* __restrict__ cls_b) {
    int row = blockIdx.x;
    int c = threadIdx.x >> 5, lane = threadIdx.x & 31;
    float s = 0.f;
    if (row < 512) {
        const float4* hr = (const float4*)(hidden + (size_t)(row < 256 ? row : row - 256) * 768);
        const float4* wr = (const float4*)(g_WcT + (size_t)c * WS + (row < 256 ? 0 : 768));
        #pragma unroll
        for (int it = 0; it < 6; it++) {
            int k4 = it * 32 + lane;
            float4 a = hr[k4], b = wr[k4];
            s += a.x * b.x + a.y * b.y + a.z * b.z + a.w * b.w;
        }
    }
    #pragma unroll
    for (int o = 16; o; o >>= 1) s += __shfl_down_sync(0xffffffffu, s, o);
    if (lane == 0) {
        const float* wt = g_WcT + (size_t)c * WS + 1536;
        if (row < 256) {
            #pragma unroll
            for (int t = 0; t < 6; t++) s += g_pool0[row * NC + t] * wt[t];
        } else if (row < 512) {
            #pragma unroll
            for (int t = 0; t < 6; t++) s += g_pool0[(row - 256) * NC + t] * wt[6 + t];
        }
        #pragma unroll
        for (int t = 0; t < 6; t++) s += g_pqr0[row * NC + t] * wt[12 + t];
        if (row == 512) s += g_fbc[c] + cls_b[c];
        g_pqr1[row * NC + c] = s;
    }
}

// ================= (6) pool1 from pqr1 =================
__global__ void k_pool1(const float* __restrict__ am) {
    int b = blockIdx.x / NC, c = blockIdx.x % NC;
    __shared__ float sp[LL], sq[LL], sm[LL];
    int k = threadIdx.x;
    sp[k] = g_pqr1[(b * LL + k) * NC + c];
    sq[k] = g_pqr1[(256 + b * LL + k) * NC + c];
    sm[k] = am[b * LL + k];
    __syncthreads();
    float r  = g_pqr1[512 * NC + c];
    float mk = sm[k], pk = sp[k], qk = sq[k];
    float mx = -INFINITY;
    #pragma unroll 4
    for (int i = 0; i < LL; i++) {
        float mi  = sm[i];
        float mv1 = (i <= k) ? mi * mk : 0.f;
        mx = fmaxf(mx, (sp[i] + qk + r) * mv1);
        float mv2 = (i >= k) ? mk * mi : 0.f;
        mx = fmaxf(mx, (pk + sq[i] + r) * mv2);
    }
    g_pool1[(b * LL + k) * NC + c] = mx;
}

// ================= (7) probs2 = A0ext @ W2 + ext1 @ Wc_tail (+ const-row) =================
__global__ void k_probs2(const float* __restrict__ hidden, const float* __restrict__ cls_b) {
    int row = blockIdx.x;
    int c = threadIdx.x >> 5, lane = threadIdx.x & 31;
    float s = 0.f;
    if (row < 512) {
        const float4* hr = (const float4*)(hidden + (size_t)(row < 256 ? row : row - 256) * 768);
        const float4* wr = (const float4*)(g_W2T + (size_t)c * WS + (row < 256 ? 0 : 768));
        #pragma unroll
        for (int it = 0; it < 6; it++) {
            int k4 = it * 32 + lane;
            float4 a = hr[k4], b = wr[k4];
            s += a.x * b.x + a.y * b.y + a.z * b.z + a.w * b.w;
        }
    }
    #pragma unroll
    for (int o = 16; o; o >>= 1) s += __shfl_down_sync(0xffffffffu, s, o);
    if (lane == 0) {
        const float* w2t = g_W2T + (size_t)c * WS + 1536;
        const float* wct = g_WcT + (size_t)c * WS + 1536;
        if (row < 256) {
            #pragma unroll
            for (int t = 0; t < 6; t++)
                s += g_pool0[row * NC + t] * w2t[t] + g_pool1[row * NC + t] * wct[t];
        } else if (row < 512) {
            #pragma unroll
            for (int t = 0; t < 6; t++)
                s += g_pool0[(row - 256) * NC + t] * w2t[6 + t] + g_pool1[(row - 256) * NC + t] * wct[6 + t];
        }
        #pragma unroll
        for (int t = 0; t < 6; t++)
            s += g_pqr0[row * NC + t] * w2t[12 + t] + g_pqr1[row * NC + t] * wct[12 + t];
        if (row == 512) s += g_fbW2[c] + g_fbc[c] + cls_b[c];
        g_pqr2f[row * NC + c] = s;
    }
}

// ================= (8) final: logits[b,i,j,c] = p + q + r =================
__global__ void k_out(float* __restrict__ out) {
    int idx = blockIdx.x * 256 + threadIdx.x;        // 0..196607 exact
    int c = idx % NC;
    int j = (idx / NC) % LL;
    int t = idx / (NC * LL);
    int i = t % LL;
    int b = t / LL;
    out[idx] = g_pqr2f[(b * LL + i) * NC + c]
             + g_pqr2f[(256 + b * LL + j) * NC + c]
             + g_pqr2f[512 * NC + c];
}

extern "C" void kernel_launch(void* const* d_in, const int* in_sizes, int n_in,
                              void* d_out, int out_size) {
    const float* hidden = (const float*)d_in[0];
    const float* am     = (const float*)d_in[1];
    const float* cls_w  = (const float*)d_in[2];
    const float* cls_b  = (const float*)d_in[3];
    const float* feat_w = (const float*)d_in[4];
    const float* feat_b = (const float*)d_in[5];

    k_cls<<<36, 256>>>(cls_w);                       // (1)
    k_pp0<<<12, 256>>>(hidden, cls_w, cls_b, am);    // (2)
    k_dotW<<<WS + 1, 192>>>(feat_w, feat_b, 0);      // (3) Wc
    k_dotW<<<WS + 1, 192>>>(feat_w, feat_b, 1);      // (4) W2  <- profiled
    k_probs1<<<513, 192>>>(hidden, cls_b);           // (5)
    k_pool1<<<12, 128>>>(am);                        // (6)
    k_probs2<<<513, 192>>>(hidden, cls_b);           // (7)
    k_out<<<768, 256>>>((float*)d_out);              // (8)
}